// round 13
// baseline (speedup 1.0000x reference)
#include <cuda_runtime.h>
#include <cuda_fp16.h>
#include <cstdint>
#include <cstddef>

// Problem constants: N=100000, D_IN=D_OUT=256, E=3.2M
#define MAXN 100352
#define MAXE 3200000
#define D    256

// Scratch (device globals; allocation is forbidden)
__device__ __align__(16) __half g_h2[(size_t)MAXN * D];  // drs[j] * (x@W^T)[j], fp16
__device__ __align__(16) __half g_xh[(size_t)MAXN * D];  // fp16(x); rows >= N stay zero
__device__ __align__(16) __half g_wh[D * D];             // fp16(W)
__device__ float g_drs[MAXN];
__device__ int   g_cnt[MAXN];
__device__ int   g_excl[MAXN];
__device__ int   g_blksum[512];
__device__ int   g_rowptr[MAXN + 1];
__device__ int   g_off[MAXN];
__device__ int   g_col[MAXE];

__device__ __forceinline__ uint32_t smem_u32(const void* p) {
    return (uint32_t)__cvta_generic_to_shared(p);
}

__device__ __forceinline__ void cp_cg16(uint32_t dst, const void* src) {
    asm volatile("cp.async.cg.shared.global [%0], [%1], 16;" :: "r"(dst), "l"(src));
}

template<int NPend>
__device__ __forceinline__ void cp_wait() {
    asm volatile("cp.async.wait_group %0;" :: "n"(NPend) : "memory");
}

// ---------------------------------------------------------------------------
// fp32 -> fp16 bulk convert (8 floats / thread)
// ---------------------------------------------------------------------------
__global__ void cvt_f2h(const float* __restrict__ in, __half* __restrict__ out, int n8) {
    int i = blockIdx.x * blockDim.x + threadIdx.x;
    if (i >= n8) return;
    float4 a = reinterpret_cast<const float4*>(in)[2 * i];
    float4 b = reinterpret_cast<const float4*>(in)[2 * i + 1];
    __half2 h[4];
    h[0] = __floats2half2_rn(a.x, a.y);
    h[1] = __floats2half2_rn(a.z, a.w);
    h[2] = __floats2half2_rn(b.x, b.y);
    h[3] = __floats2half2_rn(b.z, b.w);
    reinterpret_cast<uint4*>(out)[i] = *reinterpret_cast<uint4*>(h);
}

// ---------------------------------------------------------------------------
// Degree histogram (scalar: atomic-throughput floor, R9 confirmed)
// ---------------------------------------------------------------------------
__global__ void cnt_edges(const int* __restrict__ src, int E) {
    int e = blockIdx.x * blockDim.x + threadIdx.x;
    if (e < E) atomicAdd(&g_cnt[src[e]], 1);
}

// ---------------------------------------------------------------------------
// Prefix sum over g_cnt -> g_rowptr (+ fused drs = rsqrt(deg+1))
// ---------------------------------------------------------------------------
__global__ void scan_phase1(int N) {
    __shared__ int sh[256];
    int i = blockIdx.x * 256 + threadIdx.x;
    int v = (i < N) ? g_cnt[i] : 0;
    if (i < N) g_drs[i] = rsqrtf((float)v + 1.0f);
    sh[threadIdx.x] = v;
    __syncthreads();
#pragma unroll
    for (int off = 1; off < 256; off <<= 1) {
        int t = (threadIdx.x >= off) ? sh[threadIdx.x - off] : 0;
        __syncthreads();
        sh[threadIdx.x] += t;
        __syncthreads();
    }
    if (i < N) g_excl[i] = sh[threadIdx.x] - v;
    if (threadIdx.x == 255) g_blksum[blockIdx.x] = sh[255];
}

__global__ void scan_phase2(int nb) {
    __shared__ int sh[512];
    int t = threadIdx.x;
    int v = (t < nb) ? g_blksum[t] : 0;
    sh[t] = v;
    __syncthreads();
#pragma unroll
    for (int off = 1; off < 512; off <<= 1) {
        int u = (t >= off) ? sh[t - off] : 0;
        __syncthreads();
        sh[t] += u;
        __syncthreads();
    }
    if (t < nb) g_blksum[t] = sh[t] - v;
}

__global__ void scan_phase3(int N, int E) {
    int i = blockIdx.x * 256 + threadIdx.x;
    if (i < N) {
        int r = g_excl[i] + g_blksum[blockIdx.x];
        g_rowptr[i] = r;
        g_off[i] = r;
    }
    if (i == 0) g_rowptr[N] = E;
}

__global__ void build_col(const int* __restrict__ src, const int* __restrict__ dst, int E) {
    int e = blockIdx.x * blockDim.x + threadIdx.x;
    if (e < E) {
        int p = atomicAdd(&g_off[src[e]], 1);
        g_col[p] = dst[e];
    }
}

// ---------------------------------------------------------------------------
// Resident-W cp.async pipelined HGEMM (fp16 in, fp32 acc):
//   g_h2 = fp16( drs[i] * (xh @ wh^T) )
// 128x128 block tile, BK=32, 8 warps (2x4). W half resident in smem.
// 4 A-stages -> single sync per iteration:
//   commit(it+2) -> wait (tail-exact) -> sync -> compute(it)
// Stage safety: commit(it+2) writes stage (it+2)%4; the newest laggard reader
// compute(it-1) uses stage (it-1)%4 — different slot, no trailing sync needed.
// The sync AFTER the wait publishes every thread's completed cp.asyncs.
// ---------------------------------------------------------------------------
#define BK       32
#define ASTRIDE  40                   // A stage row stride in halves (80B)
#define ATILEH   (128 * ASTRIDE)      // halves per A stage
#define BSTRIDE  264                  // W row stride in halves (528B)
#define STAGES   4
#define GEMM_SMEM ((STAGES * ATILEH + 128 * BSTRIDE) * (int)sizeof(__half))  // 107.5KB

__global__ void __launch_bounds__(256, 2) hgemm16(const __half* __restrict__ Ah,
                                                  const __half* __restrict__ Bh,
                                                  int M) {
    extern __shared__ __half smemraw[];
    __half* Bres = smemraw + STAGES * ATILEH;   // resident W half

    const int tid  = threadIdx.x;
    const int lane = tid & 31;
    const int wid  = tid >> 5;
    const int wm   = wid >> 2;       // 0..1  (64 rows)
    const int wn   = wid & 3;        // 0..3  (32 cols)
    const int brow = blockIdx.y * 128;
    const int bcol = blockIdx.x * 128;

    float acc[4][4][4];
#pragma unroll
    for (int mt = 0; mt < 4; mt++)
#pragma unroll
        for (int nt = 0; nt < 4; nt++)
#pragma unroll
            for (int q = 0; q < 4; q++) acc[mt][nt][q] = 0.0f;

    // A-stage load coords: 128x32 halves = 512 x 16B chunks; 2 per thread.
    const int a0r = (tid)       >> 2, a0s = ((tid)       & 3) * 8;
    const int a1r = (tid + 256) >> 2, a1s = ((tid + 256) & 3) * 8;

    auto load_astage = [&](int st, int k0) {
        __half* As = smemraw + st * ATILEH;
        cp_cg16(smem_u32(As + a0r * ASTRIDE + a0s), Ah + (size_t)(brow + a0r) * 256 + k0 + a0s);
        cp_cg16(smem_u32(As + a1r * ASTRIDE + a1s), Ah + (size_t)(brow + a1r) * 256 + k0 + a1s);
        asm volatile("cp.async.commit_group;" ::: "memory");
    };

    // Group 0: resident W (128 rows x 256 halves = 4096 x 16B; 16/thread) + A stage 0.
    {
#pragma unroll
        for (int t = 0; t < 16; t++) {
            int idx = tid + t * 256;          // 0..4095
            int r = idx >> 5;                 // 0..127
            int c = (idx & 31) * 8;           // 0..248
            cp_cg16(smem_u32(Bres + r * BSTRIDE + c), Bh + (size_t)(bcol + r) * 256 + c);
        }
        __half* As = smemraw;
        cp_cg16(smem_u32(As + a0r * ASTRIDE + a0s), Ah + (size_t)(brow + a0r) * 256 + a0s);
        cp_cg16(smem_u32(As + a1r * ASTRIDE + a1s), Ah + (size_t)(brow + a1r) * 256 + a1s);
        asm volatile("cp.async.commit_group;" ::: "memory");
    }
    load_astage(1, BK);   // group 1

    // Mainloop: commit(it+2) -> wait (group it complete) -> sync -> compute(it).
#pragma unroll
    for (int it = 0; it < 8; it++) {
        if (it + 2 < 8) load_astage((it + 2) % STAGES, (it + 2) * BK);
        if (it < 6)       cp_wait<2>();
        else if (it == 6) cp_wait<1>();
        else              cp_wait<0>();
        __syncthreads();

        __half* As = smemraw + (it % STAGES) * ATILEH;
#pragma unroll
        for (int ks = 0; ks < 2; ks++) {
            const int kglob = it * BK + ks * 16;
            uint32_t a[4][4], b[4][2];
#pragma unroll
            for (int mt = 0; mt < 4; mt++) {
                uint32_t addr = smem_u32(As + (wm * 64 + mt * 16 + (lane & 15)) * ASTRIDE
                                            + ks * 16 + (lane >> 4) * 8);
                asm volatile("ldmatrix.sync.aligned.m8n8.x4.shared.b16 {%0,%1,%2,%3}, [%4];"
                             : "=r"(a[mt][0]), "=r"(a[mt][1]), "=r"(a[mt][2]), "=r"(a[mt][3])
                             : "r"(addr));
            }
#pragma unroll
            for (int nt = 0; nt < 4; nt++) {
                int l16 = lane & 15;
                uint32_t addr = smem_u32(Bres + (wn * 32 + nt * 8 + (l16 & 7)) * BSTRIDE
                                             + kglob + (l16 >> 3) * 8);
                asm volatile("ldmatrix.sync.aligned.m8n8.x2.shared.b16 {%0,%1}, [%2];"
                             : "=r"(b[nt][0]), "=r"(b[nt][1])
                             : "r"(addr));
            }
#pragma unroll
            for (int mt = 0; mt < 4; mt++)
#pragma unroll
                for (int nt = 0; nt < 4; nt++)
                    asm volatile(
                        "mma.sync.aligned.m16n8k16.row.col.f32.f16.f16.f32 "
                        "{%0,%1,%2,%3},{%4,%5,%6,%7},{%8,%9},{%0,%1,%2,%3};"
                        : "+f"(acc[mt][nt][0]), "+f"(acc[mt][nt][1]),
                          "+f"(acc[mt][nt][2]), "+f"(acc[mt][nt][3])
                        : "r"(a[mt][0]), "r"(a[mt][1]), "r"(a[mt][2]), "r"(a[mt][3]),
                          "r"(b[nt][0]), "r"(b[nt][1]));
        }
        // No trailing sync: with 4 stages, the next commit targets a stage no
        // laggard warp can still be reading.
    }

    // Epilogue: scale rows by drs, convert fp16, store to g_h2.
    const int tg = lane >> 2, tq = lane & 3;
#pragma unroll
    for (int mt = 0; mt < 4; mt++) {
        int r0 = brow + wm * 64 + mt * 16 + tg;
        int r1 = r0 + 8;
        float s0 = (r0 < M) ? g_drs[r0] : 0.f;
        float s1 = (r1 < M) ? g_drs[r1] : 0.f;
#pragma unroll
        for (int nt = 0; nt < 4; nt++) {
            int c = bcol + wn * 32 + nt * 8 + tq * 2;
            if (r0 < M)
                *reinterpret_cast<__half2*>(g_h2 + (size_t)r0 * D + c) =
                    __floats2half2_rn(acc[mt][nt][0] * s0, acc[mt][nt][1] * s0);
            if (r1 < M)
                *reinterpret_cast<__half2*>(g_h2 + (size_t)r1 * D + c) =
                    __floats2half2_rn(acc[mt][nt][2] * s1, acc[mt][nt][3] * s1);
        }
    }
}

// ---------------------------------------------------------------------------
// Aggregation (R7 version): one warp per node, 4-way unrolled gather.
// out[i] = drs[i] * ( h2[i] + sum_{j in adj(i)} h2[j] ),  h2 prescaled by drs.
// ---------------------------------------------------------------------------
__global__ void __launch_bounds__(256) aggregate(float* __restrict__ out, int N) {
    int warp = (blockIdx.x * blockDim.x + threadIdx.x) >> 5;
    int lane = threadIdx.x & 31;
    if (warp >= N) return;
    const int i = warp;

    float acc[8];
    {
        uint4 w = *reinterpret_cast<const uint4*>(g_h2 + (size_t)i * D + lane * 8);
        const __half2* hv = reinterpret_cast<const __half2*>(&w);
#pragma unroll
        for (int q = 0; q < 4; q++) {
            float2 f = __half22float2(hv[q]);
            acc[2*q + 0] = f.x;
            acc[2*q + 1] = f.y;
        }
    }

    int s = g_rowptr[i];
    int e = g_rowptr[i + 1];
    for (int b = s; b < e; b += 32) {
        int nidx = (b + lane < e) ? g_col[b + lane] : 0;
        int cnt = min(32, e - b);
        int t = 0;
        for (; t + 4 <= cnt; t += 4) {
            int j0 = __shfl_sync(0xffffffffu, nidx, t + 0);
            int j1 = __shfl_sync(0xffffffffu, nidx, t + 1);
            int j2 = __shfl_sync(0xffffffffu, nidx, t + 2);
            int j3 = __shfl_sync(0xffffffffu, nidx, t + 3);
            uint4 w0 = *reinterpret_cast<const uint4*>(g_h2 + (size_t)j0 * D + lane * 8);
            uint4 w1 = *reinterpret_cast<const uint4*>(g_h2 + (size_t)j1 * D + lane * 8);
            uint4 w2 = *reinterpret_cast<const uint4*>(g_h2 + (size_t)j2 * D + lane * 8);
            uint4 w3 = *reinterpret_cast<const uint4*>(g_h2 + (size_t)j3 * D + lane * 8);
            const __half2* h0 = reinterpret_cast<const __half2*>(&w0);
            const __half2* h1 = reinterpret_cast<const __half2*>(&w1);
            const __half2* h2 = reinterpret_cast<const __half2*>(&w2);
            const __half2* h3 = reinterpret_cast<const __half2*>(&w3);
#pragma unroll
            for (int q = 0; q < 4; q++) {
                float2 f0 = __half22float2(h0[q]);
                float2 f1 = __half22float2(h1[q]);
                float2 f2 = __half22float2(h2[q]);
                float2 f3 = __half22float2(h3[q]);
                acc[2*q + 0] += (f0.x + f1.x) + (f2.x + f3.x);
                acc[2*q + 1] += (f0.y + f1.y) + (f2.y + f3.y);
            }
        }
        for (; t < cnt; t++) {
            int j = __shfl_sync(0xffffffffu, nidx, t);
            uint4 w = *reinterpret_cast<const uint4*>(g_h2 + (size_t)j * D + lane * 8);
            const __half2* hv = reinterpret_cast<const __half2*>(&w);
#pragma unroll
            for (int q = 0; q < 4; q++) {
                float2 f = __half22float2(hv[q]);
                acc[2*q + 0] += f.x;
                acc[2*q + 1] += f.y;
            }
        }
    }

    float r = g_drs[i];
    float4 v0 = make_float4(acc[0]*r, acc[1]*r, acc[2]*r, acc[3]*r);
    float4 v1 = make_float4(acc[4]*r, acc[5]*r, acc[6]*r, acc[7]*r);
    float* orow = out + (size_t)i * D + lane * 8;
    *reinterpret_cast<float4*>(orow)     = v0;
    *reinterpret_cast<float4*>(orow + 4) = v1;
}

// ---------------------------------------------------------------------------
// Launch: (cvt x,W on s2) || (memset cnt -> cnt_edges -> scan1);
//         GEMM on s2 after scan1; (scan2/3 + build_col) on main; join -> agg.
// ---------------------------------------------------------------------------
extern "C" void kernel_launch(void* const* d_in, const int* in_sizes, int n_in,
                              void* d_out, int out_size) {
    const float* x  = (const float*)d_in[0];   // [N,256]
    const float* W  = (const float*)d_in[1];   // [256,256]
    const int*   ei = (const int*)d_in[2];     // [2,E]

    int N = in_sizes[0] / D;
    int E = in_sizes[2] / 2;
    const int* src = ei;
    const int* dst = ei + E;
    float* out = (float*)d_out;

    int nbN = (N + 255) / 256;
    int nbE = (E + 255) / 256;

    static cudaStream_t s2 = nullptr;
    static cudaEvent_t evFork = nullptr, evDrs = nullptr, evJoin = nullptr;
    static void* cntPtr = nullptr;
    static __half* xh = nullptr;
    static __half* wh = nullptr;
    if (s2 == nullptr) {
        cudaStreamCreateWithFlags(&s2, cudaStreamNonBlocking);
        cudaEventCreateWithFlags(&evFork, cudaEventDisableTiming);
        cudaEventCreateWithFlags(&evDrs, cudaEventDisableTiming);
        cudaEventCreateWithFlags(&evJoin, cudaEventDisableTiming);
        cudaFuncSetAttribute(hgemm16, cudaFuncAttributeMaxDynamicSharedMemorySize,
                             GEMM_SMEM);
        cudaGetSymbolAddress(&cntPtr, g_cnt);
        cudaGetSymbolAddress((void**)&xh, g_xh);
        cudaGetSymbolAddress((void**)&wh, g_wh);
    }

    // Fork at entry: conversions run on s2 while main builds the histogram.
    cudaEventRecord(evFork, 0);
    cudaStreamWaitEvent(s2, evFork, 0);
    cvt_f2h<<<(N * 32 + 255) / 256, 256, 0, s2>>>(x, xh, N * 32);
    cvt_f2h<<<(D * 32 + 255) / 256, 256, 0, s2>>>(W, wh, D * 32);

    // Main: degree histogram + scan_phase1 -> drs ready.
    cudaMemsetAsync(cntPtr, 0, (size_t)N * sizeof(int), 0);
    cnt_edges  <<<nbE, 256>>>(src, E);
    scan_phase1<<<nbN, 256>>>(N);
    cudaEventRecord(evDrs, 0);

    // GEMM on s2 (needs xh, wh, drs).
    cudaStreamWaitEvent(s2, evDrs, 0);
    {
        dim3 grid(D / 128, (N + 127) / 128);
        hgemm16<<<grid, 256, GEMM_SMEM, s2>>>(xh, wh, N);
    }
    cudaEventRecord(evJoin, s2);

    // Main: finish CSR build in parallel with the GEMM.
    scan_phase2<<<1,   512>>>(nbN);
    scan_phase3<<<nbN, 256>>>(N, E);
    build_col  <<<nbE, 256>>>(src, dst, E);

    // Join: aggregate needs both h2 and the CSR.
    cudaStreamWaitEvent(0, evJoin, 0);
    aggregate<<<(N + 7) / 8, 256>>>(out, N);
}

// round 14
// speedup vs baseline: 1.0590x; 1.0590x over previous
#include <cuda_runtime.h>
#include <cuda_fp16.h>
#include <cstdint>
#include <cstddef>

// Problem constants: N=100000, D_IN=D_OUT=256, E=3.2M
#define MAXN 100352
#define MAXE 3200000
#define D    256

// Scratch (device globals; allocation is forbidden)
__device__ __align__(16) __half g_h2[(size_t)MAXN * D];  // drs[j] * (x@W^T)[j], fp16
__device__ __align__(16) __half g_xh[(size_t)MAXN * D];  // fp16(x); rows >= N stay zero
__device__ __align__(16) __half g_wh[D * D];             // fp16(W)
__device__ float g_drs[MAXN];
__device__ int   g_cnt[MAXN];
__device__ int   g_excl[MAXN];
__device__ int   g_blksum[512];
__device__ int   g_rowptr[MAXN + 1];
__device__ int   g_off[MAXN];
__device__ int   g_col[MAXE];

__device__ __forceinline__ uint32_t smem_u32(const void* p) {
    return (uint32_t)__cvta_generic_to_shared(p);
}

__device__ __forceinline__ void cp_cg16(uint32_t dst, const void* src) {
    asm volatile("cp.async.cg.shared.global [%0], [%1], 16;" :: "r"(dst), "l"(src));
}

template<int NPend>
__device__ __forceinline__ void cp_wait() {
    asm volatile("cp.async.wait_group %0;" :: "n"(NPend) : "memory");
}

// ---------------------------------------------------------------------------
// fp32 -> fp16 bulk convert (8 floats / thread)
// ---------------------------------------------------------------------------
__global__ void cvt_f2h(const float* __restrict__ in, __half* __restrict__ out, int n8) {
    int i = blockIdx.x * blockDim.x + threadIdx.x;
    if (i >= n8) return;
    float4 a = reinterpret_cast<const float4*>(in)[2 * i];
    float4 b = reinterpret_cast<const float4*>(in)[2 * i + 1];
    __half2 h[4];
    h[0] = __floats2half2_rn(a.x, a.y);
    h[1] = __floats2half2_rn(a.z, a.w);
    h[2] = __floats2half2_rn(b.x, b.y);
    h[3] = __floats2half2_rn(b.z, b.w);
    reinterpret_cast<uint4*>(out)[i] = *reinterpret_cast<uint4*>(h);
}

// ---------------------------------------------------------------------------
// Degree histogram (scalar: atomic-throughput floor, R9 confirmed)
// ---------------------------------------------------------------------------
__global__ void cnt_edges(const int* __restrict__ src, int E) {
    int e = blockIdx.x * blockDim.x + threadIdx.x;
    if (e < E) atomicAdd(&g_cnt[src[e]], 1);
}

// drs = rsqrt(deg+1) — tiny kernel so the GEMM's dependency fires ASAP.
__global__ void drs_compute(int N) {
    int i = blockIdx.x * blockDim.x + threadIdx.x;
    if (i < N) g_drs[i] = rsqrtf((float)g_cnt[i] + 1.0f);
}

// ---------------------------------------------------------------------------
// Prefix sum over g_cnt -> g_rowptr
// ---------------------------------------------------------------------------
__global__ void scan_phase1(int N) {
    __shared__ int sh[256];
    int i = blockIdx.x * 256 + threadIdx.x;
    int v = (i < N) ? g_cnt[i] : 0;
    sh[threadIdx.x] = v;
    __syncthreads();
#pragma unroll
    for (int off = 1; off < 256; off <<= 1) {
        int t = (threadIdx.x >= off) ? sh[threadIdx.x - off] : 0;
        __syncthreads();
        sh[threadIdx.x] += t;
        __syncthreads();
    }
    if (i < N) g_excl[i] = sh[threadIdx.x] - v;
    if (threadIdx.x == 255) g_blksum[blockIdx.x] = sh[255];
}

__global__ void scan_phase2(int nb) {
    __shared__ int sh[512];
    int t = threadIdx.x;
    int v = (t < nb) ? g_blksum[t] : 0;
    sh[t] = v;
    __syncthreads();
#pragma unroll
    for (int off = 1; off < 512; off <<= 1) {
        int u = (t >= off) ? sh[t - off] : 0;
        __syncthreads();
        sh[t] += u;
        __syncthreads();
    }
    if (t < nb) g_blksum[t] = sh[t] - v;
}

__global__ void scan_phase3(int N, int E) {
    int i = blockIdx.x * 256 + threadIdx.x;
    if (i < N) {
        int r = g_excl[i] + g_blksum[blockIdx.x];
        g_rowptr[i] = r;
        g_off[i] = r;
    }
    if (i == 0) g_rowptr[N] = E;
}

__global__ void build_col(const int* __restrict__ src, const int* __restrict__ dst, int E) {
    int e = blockIdx.x * blockDim.x + threadIdx.x;
    if (e < E) {
        int p = atomicAdd(&g_off[src[e]], 1);
        g_col[p] = dst[e];
    }
}

// ---------------------------------------------------------------------------
// cp.async 3-stage pipelined HGEMM (fp16 in, fp32 acc) — exact R7 kernel:
//   g_h2 = fp16( drs[i] * (xh @ wh^T) )
// 128x128 block tile, BK=32, 8 warps (2x4 layout), 80B smem row stride.
// ---------------------------------------------------------------------------
#define BK      32
#define STRIDE  40
#define TILEH   (128 * STRIDE)
#define STAGES  3

__global__ void __launch_bounds__(256, 2) hgemm16(const __half* __restrict__ Ah,
                                                  const __half* __restrict__ Bh,
                                                  int M) {
    extern __shared__ __half smemraw[];

    const int tid  = threadIdx.x;
    const int lane = tid & 31;
    const int wid  = tid >> 5;
    const int wm   = wid >> 2;
    const int wn   = wid & 3;
    const int brow = blockIdx.y * 128;
    const int bcol = blockIdx.x * 128;

    float acc[4][4][4];
#pragma unroll
    for (int mt = 0; mt < 4; mt++)
#pragma unroll
        for (int nt = 0; nt < 4; nt++)
#pragma unroll
            for (int q = 0; q < 4; q++) acc[mt][nt][q] = 0.0f;

    const int c0r = (tid)       >> 2, c0s = ((tid)       & 3) * 8;
    const int c1r = (tid + 256) >> 2, c1s = ((tid + 256) & 3) * 8;

    auto load_stage = [&](int st, int k0) {
        __half* As = smemraw + st * 2 * TILEH;
        __half* Bs = As + TILEH;
        cp_cg16(smem_u32(As + c0r * STRIDE + c0s), Ah + (size_t)(brow + c0r) * 256 + k0 + c0s);
        cp_cg16(smem_u32(Bs + c0r * STRIDE + c0s), Bh + (size_t)(bcol + c0r) * 256 + k0 + c0s);
        cp_cg16(smem_u32(As + c1r * STRIDE + c1s), Ah + (size_t)(brow + c1r) * 256 + k0 + c1s);
        cp_cg16(smem_u32(Bs + c1r * STRIDE + c1s), Bh + (size_t)(bcol + c1r) * 256 + k0 + c1s);
        asm volatile("cp.async.commit_group;" ::: "memory");
    };

    auto compute_stage = [&](int st) {
        __half* As = smemraw + st * 2 * TILEH;
        __half* Bs = As + TILEH;
#pragma unroll
        for (int ks = 0; ks < 2; ks++) {
            uint32_t a[4][4], b[4][2];
#pragma unroll
            for (int mt = 0; mt < 4; mt++) {
                uint32_t addr = smem_u32(As + (wm * 64 + mt * 16 + (lane & 15)) * STRIDE
                                            + ks * 16 + (lane >> 4) * 8);
                asm volatile("ldmatrix.sync.aligned.m8n8.x4.shared.b16 {%0,%1,%2,%3}, [%4];"
                             : "=r"(a[mt][0]), "=r"(a[mt][1]), "=r"(a[mt][2]), "=r"(a[mt][3])
                             : "r"(addr));
            }
#pragma unroll
            for (int nt = 0; nt < 4; nt++) {
                int l16 = lane & 15;
                uint32_t addr = smem_u32(Bs + (wn * 32 + nt * 8 + (l16 & 7)) * STRIDE
                                            + ks * 16 + (l16 >> 3) * 8);
                asm volatile("ldmatrix.sync.aligned.m8n8.x2.shared.b16 {%0,%1}, [%2];"
                             : "=r"(b[nt][0]), "=r"(b[nt][1])
                             : "r"(addr));
            }
#pragma unroll
            for (int mt = 0; mt < 4; mt++)
#pragma unroll
                for (int nt = 0; nt < 4; nt++)
                    asm volatile(
                        "mma.sync.aligned.m16n8k16.row.col.f32.f16.f16.f32 "
                        "{%0,%1,%2,%3},{%4,%5,%6,%7},{%8,%9},{%0,%1,%2,%3};"
                        : "+f"(acc[mt][nt][0]), "+f"(acc[mt][nt][1]),
                          "+f"(acc[mt][nt][2]), "+f"(acc[mt][nt][3])
                        : "r"(a[mt][0]), "r"(a[mt][1]), "r"(a[mt][2]), "r"(a[mt][3]),
                          "r"(b[nt][0]), "r"(b[nt][1]));
        }
    };

    load_stage(0, 0);
    load_stage(1, BK);

#pragma unroll
    for (int it = 0; it < 8; it++) {
        if (it + 2 < 8) load_stage((it + 2) % STAGES, (it + 2) * BK);
        if (it < 6)      cp_wait<2>();
        else if (it == 6) cp_wait<1>();
        else              cp_wait<0>();
        __syncthreads();
        compute_stage(it % STAGES);
        __syncthreads();
    }

    const int tg = lane >> 2, tq = lane & 3;
#pragma unroll
    for (int mt = 0; mt < 4; mt++) {
        int r0 = brow + wm * 64 + mt * 16 + tg;
        int r1 = r0 + 8;
        float s0 = (r0 < M) ? g_drs[r0] : 0.f;
        float s1 = (r1 < M) ? g_drs[r1] : 0.f;
#pragma unroll
        for (int nt = 0; nt < 4; nt++) {
            int c = bcol + wn * 32 + nt * 8 + tq * 2;
            if (r0 < M)
                *reinterpret_cast<__half2*>(g_h2 + (size_t)r0 * D + c) =
                    __floats2half2_rn(acc[mt][nt][0] * s0, acc[mt][nt][1] * s0);
            if (r1 < M)
                *reinterpret_cast<__half2*>(g_h2 + (size_t)r1 * D + c) =
                    __floats2half2_rn(acc[mt][nt][2] * s1, acc[mt][nt][3] * s1);
        }
    }
}

// ---------------------------------------------------------------------------
// Aggregation: one warp per node, 4-way unrolled gather (h2 prescaled by drs).
// out[i] = drs[i] * ( h2[i] + sum_{j in adj(i)} h2[j] )
// g_col read with .cs (stream, read-once); out written with .cs (evict-first)
// so the 100MB of write-once output doesn't evict the L2-resident h2.
// ---------------------------------------------------------------------------
__global__ void __launch_bounds__(256) aggregate(float* __restrict__ out, int N) {
    int warp = (blockIdx.x * blockDim.x + threadIdx.x) >> 5;
    int lane = threadIdx.x & 31;
    if (warp >= N) return;
    const int i = warp;

    float acc[8];
    {
        uint4 w = *reinterpret_cast<const uint4*>(g_h2 + (size_t)i * D + lane * 8);
        const __half2* hv = reinterpret_cast<const __half2*>(&w);
#pragma unroll
        for (int q = 0; q < 4; q++) {
            float2 f = __half22float2(hv[q]);
            acc[2*q + 0] = f.x;
            acc[2*q + 1] = f.y;
        }
    }

    int s = g_rowptr[i];
    int e = g_rowptr[i + 1];
    for (int b = s; b < e; b += 32) {
        int nidx = (b + lane < e) ? __ldcs(&g_col[b + lane]) : 0;
        int cnt = min(32, e - b);
        int t = 0;
        for (; t + 4 <= cnt; t += 4) {
            int j0 = __shfl_sync(0xffffffffu, nidx, t + 0);
            int j1 = __shfl_sync(0xffffffffu, nidx, t + 1);
            int j2 = __shfl_sync(0xffffffffu, nidx, t + 2);
            int j3 = __shfl_sync(0xffffffffu, nidx, t + 3);
            uint4 w0 = *reinterpret_cast<const uint4*>(g_h2 + (size_t)j0 * D + lane * 8);
            uint4 w1 = *reinterpret_cast<const uint4*>(g_h2 + (size_t)j1 * D + lane * 8);
            uint4 w2 = *reinterpret_cast<const uint4*>(g_h2 + (size_t)j2 * D + lane * 8);
            uint4 w3 = *reinterpret_cast<const uint4*>(g_h2 + (size_t)j3 * D + lane * 8);
            const __half2* h0 = reinterpret_cast<const __half2*>(&w0);
            const __half2* h1 = reinterpret_cast<const __half2*>(&w1);
            const __half2* h2 = reinterpret_cast<const __half2*>(&w2);
            const __half2* h3 = reinterpret_cast<const __half2*>(&w3);
#pragma unroll
            for (int q = 0; q < 4; q++) {
                float2 f0 = __half22float2(h0[q]);
                float2 f1 = __half22float2(h1[q]);
                float2 f2 = __half22float2(h2[q]);
                float2 f3 = __half22float2(h3[q]);
                acc[2*q + 0] += (f0.x + f1.x) + (f2.x + f3.x);
                acc[2*q + 1] += (f0.y + f1.y) + (f2.y + f3.y);
            }
        }
        for (; t < cnt; t++) {
            int j = __shfl_sync(0xffffffffu, nidx, t);
            uint4 w = *reinterpret_cast<const uint4*>(g_h2 + (size_t)j * D + lane * 8);
            const __half2* hv = reinterpret_cast<const __half2*>(&w);
#pragma unroll
            for (int q = 0; q < 4; q++) {
                float2 f = __half22float2(hv[q]);
                acc[2*q + 0] += f.x;
                acc[2*q + 1] += f.y;
            }
        }
    }

    float r = g_drs[i];
    float4 v0 = make_float4(acc[0]*r, acc[1]*r, acc[2]*r, acc[3]*r);
    float4 v1 = make_float4(acc[4]*r, acc[5]*r, acc[6]*r, acc[7]*r);
    float* orow = out + (size_t)i * D + lane * 8;
    __stcs(reinterpret_cast<float4*>(orow),     v0);
    __stcs(reinterpret_cast<float4*>(orow + 4), v1);
}

// ---------------------------------------------------------------------------
// Launch: (cvt x,W on s2) || (memset cnt -> cnt_edges -> drs);
//         GEMM on s2 after drs; (scan1/2/3 + build_col) on main; join -> agg.
// ---------------------------------------------------------------------------
extern "C" void kernel_launch(void* const* d_in, const int* in_sizes, int n_in,
                              void* d_out, int out_size) {
    const float* x  = (const float*)d_in[0];   // [N,256]
    const float* W  = (const float*)d_in[1];   // [256,256]
    const int*   ei = (const int*)d_in[2];     // [2,E]

    int N = in_sizes[0] / D;
    int E = in_sizes[2] / 2;
    const int* src = ei;
    const int* dst = ei + E;
    float* out = (float*)d_out;

    int nbN = (N + 255) / 256;
    int nbE = (E + 255) / 256;

    static cudaStream_t s2 = nullptr;
    static cudaEvent_t evFork = nullptr, evDrs = nullptr, evJoin = nullptr;
    static void* cntPtr = nullptr;
    static __half* xh = nullptr;
    static __half* wh = nullptr;
    if (s2 == nullptr) {
        cudaStreamCreateWithFlags(&s2, cudaStreamNonBlocking);
        cudaEventCreateWithFlags(&evFork, cudaEventDisableTiming);
        cudaEventCreateWithFlags(&evDrs, cudaEventDisableTiming);
        cudaEventCreateWithFlags(&evJoin, cudaEventDisableTiming);
        cudaFuncSetAttribute(hgemm16, cudaFuncAttributeMaxDynamicSharedMemorySize,
                             STAGES * 2 * TILEH * (int)sizeof(__half));
        cudaGetSymbolAddress(&cntPtr, g_cnt);
        cudaGetSymbolAddress((void**)&xh, g_xh);
        cudaGetSymbolAddress((void**)&wh, g_wh);
    }

    // Fork at entry: conversions run on s2 while main builds the histogram.
    cudaEventRecord(evFork, 0);
    cudaStreamWaitEvent(s2, evFork, 0);
    cvt_f2h<<<(N * 32 + 255) / 256, 256, 0, s2>>>(x, xh, N * 32);
    cvt_f2h<<<(D * 32 + 255) / 256, 256, 0, s2>>>(W, wh, D * 32);

    // Main: degree histogram -> drs (tiny) -> event fires ASAP.
    cudaMemsetAsync(cntPtr, 0, (size_t)N * sizeof(int), 0);
    cnt_edges  <<<nbE, 256>>>(src, E);
    drs_compute<<<nbN, 256>>>(N);
    cudaEventRecord(evDrs, 0);

    // GEMM on s2 (needs xh, wh, drs).
    cudaStreamWaitEvent(s2, evDrs, 0);
    {
        dim3 grid(D / 128, (N + 127) / 128);
        hgemm16<<<grid, 256, STAGES * 2 * TILEH * (int)sizeof(__half), s2>>>(xh, wh, N);
    }
    cudaEventRecord(evJoin, s2);

    // Main: CSR build in parallel with the GEMM.
    scan_phase1<<<nbN, 256>>>(N);
    scan_phase2<<<1,   512>>>(nbN);
    scan_phase3<<<nbN, 256>>>(N, E);
    build_col  <<<nbE, 256>>>(src, dst, E);

    // Join: aggregate needs both h2 and the CSR.
    cudaStreamWaitEvent(0, evJoin, 0);
    aggregate<<<(N + 7) / 8, 256>>>(out, N);
}

// round 15
// speedup vs baseline: 1.0773x; 1.0172x over previous
#include <cuda_runtime.h>
#include <cuda_fp16.h>
#include <cstdint>
#include <cstddef>

// Problem constants: N=100000, D_IN=D_OUT=256, E=3.2M
#define MAXN 100352
#define MAXE 3200000
#define D    256

// Scratch (device globals; allocation is forbidden)
__device__ __align__(16) __half g_h2[(size_t)MAXN * D];  // drs[j] * (x@W^T)[j], fp16
__device__ __align__(16) __half g_xh[(size_t)MAXN * D];  // fp16(x); rows >= N stay zero
__device__ __align__(16) __half g_wh[D * D];             // fp16(W)
__device__ float g_drs[MAXN];
__device__ int   g_cnt4[4 * MAXN];   // 4-way split histogram (contention /4)
__device__ int   g_cnt[MAXN];        // merged degree (written by drs_compute)
__device__ int   g_excl[MAXN];
__device__ int   g_blksum[512];
__device__ int   g_rowptr[MAXN + 1];
__device__ int   g_off[MAXN];
__device__ int   g_col[MAXE];

__device__ __forceinline__ uint32_t smem_u32(const void* p) {
    return (uint32_t)__cvta_generic_to_shared(p);
}

__device__ __forceinline__ void cp_cg16(uint32_t dst, const void* src) {
    asm volatile("cp.async.cg.shared.global [%0], [%1], 16;" :: "r"(dst), "l"(src));
}

template<int NPend>
__device__ __forceinline__ void cp_wait() {
    asm volatile("cp.async.wait_group %0;" :: "n"(NPend) : "memory");
}

// ---------------------------------------------------------------------------
// fp32 -> fp16 bulk convert (8 floats / thread)
// ---------------------------------------------------------------------------
__global__ void cvt_f2h(const float* __restrict__ in, __half* __restrict__ out, int n8) {
    int i = blockIdx.x * blockDim.x + threadIdx.x;
    if (i >= n8) return;
    float4 a = reinterpret_cast<const float4*>(in)[2 * i];
    float4 b = reinterpret_cast<const float4*>(in)[2 * i + 1];
    __half2 h[4];
    h[0] = __floats2half2_rn(a.x, a.y);
    h[1] = __floats2half2_rn(a.z, a.w);
    h[2] = __floats2half2_rn(b.x, b.y);
    h[3] = __floats2half2_rn(b.z, b.w);
    reinterpret_cast<uint4*>(out)[i] = *reinterpret_cast<uint4*>(h);
}

// ---------------------------------------------------------------------------
// Degree histogram, 4-way split: per-address contention drops 32 -> 8.
// ---------------------------------------------------------------------------
__global__ void cnt_edges(const int* __restrict__ src, int E) {
    int e = blockIdx.x * blockDim.x + threadIdx.x;
    if (e < E) atomicAdd(&g_cnt4[((e & 3) << 17) /* *MAXN=131072? no */], 1);
}

// NOTE: MAXN is not a power of two; index arithmetic done explicitly below.
__global__ void cnt_edges4(const int* __restrict__ src, int E) {
    int e = blockIdx.x * blockDim.x + threadIdx.x;
    if (e < E) {
        int b = e & 3;
        atomicAdd(&g_cnt4[b * MAXN + src[e]], 1);
    }
}

// drs = rsqrt(deg+1); also writes merged g_cnt for the scan.
__global__ void drs_compute(int N) {
    int i = blockIdx.x * blockDim.x + threadIdx.x;
    if (i < N) {
        int c = g_cnt4[i] + g_cnt4[MAXN + i] + g_cnt4[2 * MAXN + i] + g_cnt4[3 * MAXN + i];
        g_cnt[i] = c;
        g_drs[i] = rsqrtf((float)c + 1.0f);
    }
}

// ---------------------------------------------------------------------------
// Prefix sum over g_cnt -> g_rowptr
// ---------------------------------------------------------------------------
__global__ void scan_phase1(int N) {
    __shared__ int sh[256];
    int i = blockIdx.x * 256 + threadIdx.x;
    int v = (i < N) ? g_cnt[i] : 0;
    sh[threadIdx.x] = v;
    __syncthreads();
#pragma unroll
    for (int off = 1; off < 256; off <<= 1) {
        int t = (threadIdx.x >= off) ? sh[threadIdx.x - off] : 0;
        __syncthreads();
        sh[threadIdx.x] += t;
        __syncthreads();
    }
    if (i < N) g_excl[i] = sh[threadIdx.x] - v;
    if (threadIdx.x == 255) g_blksum[blockIdx.x] = sh[255];
}

__global__ void scan_phase2(int nb) {
    __shared__ int sh[512];
    int t = threadIdx.x;
    int v = (t < nb) ? g_blksum[t] : 0;
    sh[t] = v;
    __syncthreads();
#pragma unroll
    for (int off = 1; off < 512; off <<= 1) {
        int u = (t >= off) ? sh[t - off] : 0;
        __syncthreads();
        sh[t] += u;
        __syncthreads();
    }
    if (t < nb) g_blksum[t] = sh[t] - v;
}

__global__ void scan_phase3(int N, int E) {
    int i = blockIdx.x * 256 + threadIdx.x;
    if (i < N) {
        int r = g_excl[i] + g_blksum[blockIdx.x];
        g_rowptr[i] = r;
        g_off[i] = r;
    }
    if (i == 0) g_rowptr[N] = E;
}

__global__ void build_col(const int* __restrict__ src, const int* __restrict__ dst, int E) {
    int e = blockIdx.x * blockDim.x + threadIdx.x;
    if (e < E) {
        int p = atomicAdd(&g_off[src[e]], 1);
        g_col[p] = dst[e];
    }
}

// ---------------------------------------------------------------------------
// cp.async 3-stage pipelined HGEMM (fp16 in, fp32 acc):
//   g_h2 = fp16( drs[i] * (xh @ wh^T) )
// 128x128 block tile, BK=32, 8 warps (2x4 layout), 80B smem row stride.
// B fragments loaded via paired ldmatrix.x4 (2 per k-step instead of 4 x2).
// ---------------------------------------------------------------------------
#define BK      32
#define STRIDE  40
#define TILEH   (128 * STRIDE)
#define STAGES  3

__global__ void __launch_bounds__(256, 2) hgemm16(const __half* __restrict__ Ah,
                                                  const __half* __restrict__ Bh,
                                                  int M) {
    extern __shared__ __half smemraw[];

    const int tid  = threadIdx.x;
    const int lane = tid & 31;
    const int wid  = tid >> 5;
    const int wm   = wid >> 2;
    const int wn   = wid & 3;
    const int brow = blockIdx.y * 128;
    const int bcol = blockIdx.x * 128;

    float acc[4][4][4];
#pragma unroll
    for (int mt = 0; mt < 4; mt++)
#pragma unroll
        for (int nt = 0; nt < 4; nt++)
#pragma unroll
            for (int q = 0; q < 4; q++) acc[mt][nt][q] = 0.0f;

    const int c0r = (tid)       >> 2, c0s = ((tid)       & 3) * 8;
    const int c1r = (tid + 256) >> 2, c1s = ((tid + 256) & 3) * 8;

    auto load_stage = [&](int st, int k0) {
        __half* As = smemraw + st * 2 * TILEH;
        __half* Bs = As + TILEH;
        cp_cg16(smem_u32(As + c0r * STRIDE + c0s), Ah + (size_t)(brow + c0r) * 256 + k0 + c0s);
        cp_cg16(smem_u32(Bs + c0r * STRIDE + c0s), Bh + (size_t)(bcol + c0r) * 256 + k0 + c0s);
        cp_cg16(smem_u32(As + c1r * STRIDE + c1s), Ah + (size_t)(brow + c1r) * 256 + k0 + c1s);
        cp_cg16(smem_u32(Bs + c1r * STRIDE + c1s), Bh + (size_t)(bcol + c1r) * 256 + k0 + c1s);
        asm volatile("cp.async.commit_group;" ::: "memory");
    };

    auto compute_stage = [&](int st) {
        __half* As = smemraw + st * 2 * TILEH;
        __half* Bs = As + TILEH;
#pragma unroll
        for (int ks = 0; ks < 2; ks++) {
            uint32_t a[4][4], b[4][2];
#pragma unroll
            for (int mt = 0; mt < 4; mt++) {
                uint32_t addr = smem_u32(As + (wm * 64 + mt * 16 + (lane & 15)) * STRIDE
                                            + ks * 16 + (lane >> 4) * 8);
                asm volatile("ldmatrix.sync.aligned.m8n8.x4.shared.b16 {%0,%1,%2,%3}, [%4];"
                             : "=r"(a[mt][0]), "=r"(a[mt][1]), "=r"(a[mt][2]), "=r"(a[mt][3])
                             : "r"(addr));
            }
            // B: two x4 loads, each covering an adjacent n-tile pair.
            // lanes 0-7:  ntp tile rows,  k+0   -> r0 = b[2p][0]
            // lanes 8-15: ntp tile rows,  k+8   -> r1 = b[2p][1]
            // lanes 16-23: ntp+1 rows,    k+0   -> r2 = b[2p+1][0]
            // lanes 24-31: ntp+1 rows,    k+8   -> r3 = b[2p+1][1]
#pragma unroll
            for (int ntp = 0; ntp < 2; ntp++) {
                int row = wn * 32 + ntp * 16 + (lane >> 4) * 8 + (lane & 7);
                int kof = ks * 16 + ((lane >> 3) & 1) * 8;
                uint32_t addr = smem_u32(Bs + row * STRIDE + kof);
                asm volatile("ldmatrix.sync.aligned.m8n8.x4.shared.b16 {%0,%1,%2,%3}, [%4];"
                             : "=r"(b[2*ntp][0]), "=r"(b[2*ntp][1]),
                               "=r"(b[2*ntp+1][0]), "=r"(b[2*ntp+1][1])
                             : "r"(addr));
            }
#pragma unroll
            for (int mt = 0; mt < 4; mt++)
#pragma unroll
                for (int nt = 0; nt < 4; nt++)
                    asm volatile(
                        "mma.sync.aligned.m16n8k16.row.col.f32.f16.f16.f32 "
                        "{%0,%1,%2,%3},{%4,%5,%6,%7},{%8,%9},{%0,%1,%2,%3};"
                        : "+f"(acc[mt][nt][0]), "+f"(acc[mt][nt][1]),
                          "+f"(acc[mt][nt][2]), "+f"(acc[mt][nt][3])
                        : "r"(a[mt][0]), "r"(a[mt][1]), "r"(a[mt][2]), "r"(a[mt][3]),
                          "r"(b[nt][0]), "r"(b[nt][1]));
        }
    };

    load_stage(0, 0);
    load_stage(1, BK);

#pragma unroll
    for (int it = 0; it < 8; it++) {
        if (it + 2 < 8) load_stage((it + 2) % STAGES, (it + 2) * BK);
        if (it < 6)      cp_wait<2>();
        else if (it == 6) cp_wait<1>();
        else              cp_wait<0>();
        __syncthreads();
        compute_stage(it % STAGES);
        __syncthreads();
    }

    const int tg = lane >> 2, tq = lane & 3;
#pragma unroll
    for (int mt = 0; mt < 4; mt++) {
        int r0 = brow + wm * 64 + mt * 16 + tg;
        int r1 = r0 + 8;
        float s0 = (r0 < M) ? g_drs[r0] : 0.f;
        float s1 = (r1 < M) ? g_drs[r1] : 0.f;
#pragma unroll
        for (int nt = 0; nt < 4; nt++) {
            int c = bcol + wn * 32 + nt * 8 + tq * 2;
            if (r0 < M)
                *reinterpret_cast<__half2*>(g_h2 + (size_t)r0 * D + c) =
                    __floats2half2_rn(acc[mt][nt][0] * s0, acc[mt][nt][1] * s0);
            if (r1 < M)
                *reinterpret_cast<__half2*>(g_h2 + (size_t)r1 * D + c) =
                    __floats2half2_rn(acc[mt][nt][2] * s1, acc[mt][nt][3] * s1);
        }
    }
}

// ---------------------------------------------------------------------------
// Aggregation: one warp per node, 4-way unrolled gather (h2 prescaled by drs).
// out[i] = drs[i] * ( h2[i] + sum_{j in adj(i)} h2[j] )
// ---------------------------------------------------------------------------
__global__ void __launch_bounds__(256) aggregate(float* __restrict__ out, int N) {
    int warp = (blockIdx.x * blockDim.x + threadIdx.x) >> 5;
    int lane = threadIdx.x & 31;
    if (warp >= N) return;
    const int i = warp;

    float acc[8];
    {
        uint4 w = *reinterpret_cast<const uint4*>(g_h2 + (size_t)i * D + lane * 8);
        const __half2* hv = reinterpret_cast<const __half2*>(&w);
#pragma unroll
        for (int q = 0; q < 4; q++) {
            float2 f = __half22float2(hv[q]);
            acc[2*q + 0] = f.x;
            acc[2*q + 1] = f.y;
        }
    }

    int s = g_rowptr[i];
    int e = g_rowptr[i + 1];
    for (int b = s; b < e; b += 32) {
        int nidx = (b + lane < e) ? __ldcs(&g_col[b + lane]) : 0;
        int cnt = min(32, e - b);
        int t = 0;
        for (; t + 4 <= cnt; t += 4) {
            int j0 = __shfl_sync(0xffffffffu, nidx, t + 0);
            int j1 = __shfl_sync(0xffffffffu, nidx, t + 1);
            int j2 = __shfl_sync(0xffffffffu, nidx, t + 2);
            int j3 = __shfl_sync(0xffffffffu, nidx, t + 3);
            uint4 w0 = *reinterpret_cast<const uint4*>(g_h2 + (size_t)j0 * D + lane * 8);
            uint4 w1 = *reinterpret_cast<const uint4*>(g_h2 + (size_t)j1 * D + lane * 8);
            uint4 w2 = *reinterpret_cast<const uint4*>(g_h2 + (size_t)j2 * D + lane * 8);
            uint4 w3 = *reinterpret_cast<const uint4*>(g_h2 + (size_t)j3 * D + lane * 8);
            const __half2* h0 = reinterpret_cast<const __half2*>(&w0);
            const __half2* h1 = reinterpret_cast<const __half2*>(&w1);
            const __half2* h2 = reinterpret_cast<const __half2*>(&w2);
            const __half2* h3 = reinterpret_cast<const __half2*>(&w3);
#pragma unroll
            for (int q = 0; q < 4; q++) {
                float2 f0 = __half22float2(h0[q]);
                float2 f1 = __half22float2(h1[q]);
                float2 f2 = __half22float2(h2[q]);
                float2 f3 = __half22float2(h3[q]);
                acc[2*q + 0] += (f0.x + f1.x) + (f2.x + f3.x);
                acc[2*q + 1] += (f0.y + f1.y) + (f2.y + f3.y);
            }
        }
        for (; t < cnt; t++) {
            int j = __shfl_sync(0xffffffffu, nidx, t);
            uint4 w = *reinterpret_cast<const uint4*>(g_h2 + (size_t)j * D + lane * 8);
            const __half2* hv = reinterpret_cast<const __half2*>(&w);
#pragma unroll
            for (int q = 0; q < 4; q++) {
                float2 f = __half22float2(hv[q]);
                acc[2*q + 0] += f.x;
                acc[2*q + 1] += f.y;
            }
        }
    }

    float r = g_drs[i];
    float4 v0 = make_float4(acc[0]*r, acc[1]*r, acc[2]*r, acc[3]*r);
    float4 v1 = make_float4(acc[4]*r, acc[5]*r, acc[6]*r, acc[7]*r);
    float* orow = out + (size_t)i * D + lane * 8;
    __stcs(reinterpret_cast<float4*>(orow),     v0);
    __stcs(reinterpret_cast<float4*>(orow + 4), v1);
}

// ---------------------------------------------------------------------------
// Launch: (cvt x,W on s2) || (memset cnt4 -> cnt_edges4 -> drs);
//         GEMM on s2 after drs; (scan1/2/3 + build_col) on main; join -> agg.
// ---------------------------------------------------------------------------
extern "C" void kernel_launch(void* const* d_in, const int* in_sizes, int n_in,
                              void* d_out, int out_size) {
    const float* x  = (const float*)d_in[0];   // [N,256]
    const float* W  = (const float*)d_in[1];   // [256,256]
    const int*   ei = (const int*)d_in[2];     // [2,E]

    int N = in_sizes[0] / D;
    int E = in_sizes[2] / 2;
    const int* src = ei;
    const int* dst = ei + E;
    float* out = (float*)d_out;

    int nbN = (N + 255) / 256;
    int nbE = (E + 255) / 256;

    static cudaStream_t s2 = nullptr;
    static cudaEvent_t evFork = nullptr, evDrs = nullptr, evJoin = nullptr;
    static void* cnt4Ptr = nullptr;
    static __half* xh = nullptr;
    static __half* wh = nullptr;
    if (s2 == nullptr) {
        cudaStreamCreateWithFlags(&s2, cudaStreamNonBlocking);
        cudaEventCreateWithFlags(&evFork, cudaEventDisableTiming);
        cudaEventCreateWithFlags(&evDrs, cudaEventDisableTiming);
        cudaEventCreateWithFlags(&evJoin, cudaEventDisableTiming);
        cudaFuncSetAttribute(hgemm16, cudaFuncAttributeMaxDynamicSharedMemorySize,
                             STAGES * 2 * TILEH * (int)sizeof(__half));
        cudaGetSymbolAddress(&cnt4Ptr, g_cnt4);
        cudaGetSymbolAddress((void**)&xh, g_xh);
        cudaGetSymbolAddress((void**)&wh, g_wh);
    }

    // Fork at entry: conversions run on s2 while main builds the histogram.
    cudaEventRecord(evFork, 0);
    cudaStreamWaitEvent(s2, evFork, 0);
    cvt_f2h<<<(N * 32 + 255) / 256, 256, 0, s2>>>(x, xh, N * 32);
    cvt_f2h<<<(D * 32 + 255) / 256, 256, 0, s2>>>(W, wh, D * 32);

    // Main: 4-way split histogram -> drs (merges buckets) -> event.
    cudaMemsetAsync(cnt4Ptr, 0, (size_t)4 * MAXN * sizeof(int), 0);
    cnt_edges4 <<<nbE, 256>>>(src, E);
    drs_compute<<<nbN, 256>>>(N);
    cudaEventRecord(evDrs, 0);

    // GEMM on s2 (needs xh, wh, drs).
    cudaStreamWaitEvent(s2, evDrs, 0);
    {
        dim3 grid(D / 128, (N + 127) / 128);
        hgemm16<<<grid, 256, STAGES * 2 * TILEH * (int)sizeof(__half), s2>>>(xh, wh, N);
    }
    cudaEventRecord(evJoin, s2);

    // Main: CSR build in parallel with the GEMM.
    scan_phase1<<<nbN, 256>>>(N);
    scan_phase2<<<1,   512>>>(nbN);
    scan_phase3<<<nbN, 256>>>(N, E);
    build_col  <<<nbE, 256>>>(src, dst, E);

    // Join: aggregate needs both h2 and the CSR.
    cudaStreamWaitEvent(0, evJoin, 0);
    aggregate<<<(N + 7) / 8, 256>>>(out, N);
}